// round 7
// baseline (speedup 1.0000x reference)
#include <cuda_runtime.h>
#include <math_constants.h>
#include <cstdint>

// Problem constants
constexpr int B = 32, S = 4, K = 11, C = 9, H = 128, W = 128;
constexpr int HW = H * W;          // 16384
constexpr int BSK = B * S * K;     // 1408
constexpr int BS = B * S;          // 128
constexpr int CH4 = 512;           // float4s per chunk (8 KB)
constexpr int NCH = HW / 4 / CH4;  // 8 chunks per plane

// ---- mbarrier / bulk-copy PTX helpers ----
__device__ __forceinline__ uint32_t smem_u32(const void* p) {
    return (uint32_t)__cvta_generic_to_shared(p);
}
#define MBAR_INIT(addr, cnt) \
    asm volatile("mbarrier.init.shared.b64 [%0], %1;" :: "r"(addr), "r"(cnt) : "memory")
#define MBAR_EXPECT_TX(addr, bytes) \
    asm volatile("mbarrier.arrive.expect_tx.shared.b64 _, [%0], %1;" \
                 :: "r"(addr), "r"(bytes) : "memory")
#define MBAR_WAIT(addr, parity) do {                                          \
    uint32_t _m = (addr), _p = (parity), _done;                               \
    asm volatile("{\n\t.reg .pred p;\n\t"                                     \
        "mbarrier.try_wait.parity.acquire.cta.shared::cta.b64 p, [%1], %2;\n\t" \
        "selp.b32 %0, 1, 0, p;\n\t}"                                          \
        : "=r"(_done) : "r"(_m), "r"(_p) : "memory");                         \
    if (!_done) {                                                             \
        asm volatile("{\n\t.reg .pred P1;\n\t"                                \
            "WL_%=:\n\t"                                                      \
            "mbarrier.try_wait.parity.acquire.cta.shared::cta.b64 P1, [%0], %1, 0x989680;\n\t" \
            "@P1 bra.uni WD_%=;\n\t"                                          \
            "bra.uni WL_%=;\n\t"                                              \
            "WD_%=:\n\t}" :: "r"(_m), "r"(_p) : "memory");                    \
    }                                                                         \
} while (0)

__device__ __forceinline__ void bulk_g2s(uint32_t dst, const void* src,
                                         uint32_t bytes, uint32_t mbar) {
    asm volatile(
        "cp.async.bulk.shared::cta.global.mbarrier::complete_tx::bytes "
        "[%0], [%1], %2, [%3];"
        :: "r"(dst), "l"(src), "r"(bytes), "r"(mbar) : "memory");
}

// Zero-init the output (poisoned by harness; we accumulate with atomics).
__global__ __launch_bounds__(256) void kp_zero_kernel(float* __restrict__ out) {
    out[threadIdx.x] = 0.0f;       // exactly 2*BS = 256 elements
}

// One block per (b,s,k). Double-buffered cp.async.bulk pipeline: DMA engine
// streams pred+gt chunks into smem; threads compute sumsq+argmax from smem.
// Fused label-loss epilogue as before.
__global__ __launch_bounds__(256) void kp_fused_kernel(
    const float* __restrict__ hm_preds,   // [B,S,K,H,W]
    const float* __restrict__ lb_preds,   // [B,S,C,H,W]
    const float* __restrict__ heatmaps,   // [B,K,H,W]
    const float* __restrict__ labels,     // [B,K,11]
    float* __restrict__ out)              // [2*B*S]: [hm | lb]
{
    const int blk = blockIdx.x;           // b*S*K + s*K + k
    const int k = blk % K;
    const int bs = blk / K;               // b*S + s
    const int b = bs / S;

    __shared__ __align__(16) float4 sp[2][CH4];   // pred chunks
    __shared__ __align__(16) float4 sgm[2][CH4];  // gt chunks
    __shared__ __align__(8) unsigned long long mbar[2];
    __shared__ float s_sq[8];
    __shared__ float s_mx[8];
    __shared__ int   s_mi[8];

    const float* __restrict__ gp = hm_preds + (size_t)blk * HW;
    const float* __restrict__ gg = heatmaps + ((size_t)b * K + k) * HW;

    const int tid = threadIdx.x;
    const int wid = tid >> 5, lane = tid & 31;

    if (tid == 0) {
        MBAR_INIT(smem_u32(&mbar[0]), 1);
        MBAR_INIT(smem_u32(&mbar[1]), 1);
        asm volatile("fence.proxy.async.shared::cta;" ::: "memory");
    }
    __syncthreads();

    if (tid == 0) {
        // Prologue: fill both slots (chunks 0 and 1)
        #pragma unroll
        for (int st = 0; st < 2; st++) {
            const uint32_t mb = smem_u32(&mbar[st]);
            MBAR_EXPECT_TX(mb, 2 * CH4 * 16);
            bulk_g2s(smem_u32(&sp[st][0]),  gp + (size_t)st * CH4 * 4, CH4 * 16, mb);
            bulk_g2s(smem_u32(&sgm[st][0]), gg + (size_t)st * CH4 * 4, CH4 * 16, mb);
        }
    }

    float sq = 0.0f;
    float mx = -CUDART_INF_F;
    int   mi = 0;

    #pragma unroll 1
    for (int st = 0; st < NCH; st++) {
        const int slot   = st & 1;
        const int parity = (st >> 1) & 1;
        MBAR_WAIT(smem_u32(&mbar[slot]), parity);

        #pragma unroll
        for (int j = 0; j < CH4 / 256; j++) {
            const int il = j * 256 + tid;
            const float4 pp = sp[slot][il];
            const float4 gv = sgm[slot][il];
            float d0 = pp.x - gv.x, d1 = pp.y - gv.y;
            float d2 = pp.z - gv.z, d3 = pp.w - gv.w;
            sq += d0 * d0 + d1 * d1 + d2 * d2 + d3 * d3;
            const int base = (st * CH4 + il) * 4;   // ascending per thread
            if (pp.x > mx) { mx = pp.x; mi = base;     }
            if (pp.y > mx) { mx = pp.y; mi = base + 1; }
            if (pp.z > mx) { mx = pp.z; mi = base + 2; }
            if (pp.w > mx) { mx = pp.w; mi = base + 3; }
        }
        __syncthreads();   // slot fully consumed by all threads

        const int nst = st + 2;
        if (tid == 0 && nst < NCH) {
            const uint32_t mb = smem_u32(&mbar[slot]);
            MBAR_EXPECT_TX(mb, 2 * CH4 * 16);
            bulk_g2s(smem_u32(&sp[slot][0]),  gp + (size_t)nst * CH4 * 4, CH4 * 16, mb);
            bulk_g2s(smem_u32(&sgm[slot][0]), gg + (size_t)nst * CH4 * 4, CH4 * 16, mb);
        }
    }

    // Warp reduction (sum + argmax with first-index tiebreak)
    #pragma unroll
    for (int off = 16; off > 0; off >>= 1) {
        sq += __shfl_down_sync(0xFFFFFFFFu, sq, off);
        float omx = __shfl_down_sync(0xFFFFFFFFu, mx, off);
        int   omi = __shfl_down_sync(0xFFFFFFFFu, mi, off);
        if (omx > mx || (omx == mx && omi < mi)) { mx = omx; mi = omi; }
    }
    if (lane == 0) { s_sq[wid] = sq; s_mx[wid] = mx; s_mi[wid] = mi; }
    __syncthreads();

    if (wid == 0) {
        sq = (lane < 8) ? s_sq[lane] : 0.0f;
        mx = (lane < 8) ? s_mx[lane] : -CUDART_INF_F;
        mi = (lane < 8) ? s_mi[lane] : 0x7FFFFFFF;
        #pragma unroll
        for (int off = 4; off > 0; off >>= 1) {
            sq += __shfl_down_sync(0xFFFFFFFFu, sq, off);
            float omx = __shfl_down_sync(0xFFFFFFFFu, mx, off);
            int   omi = __shfl_down_sync(0xFFFFFFFFu, mi, off);
            if (omx > mx || (omx == mx && omi < mi)) { mx = omx; mi = omi; }
        }

        // ---- Label-loss epilogue (fused): broadcast within warp 0 ----
        sq = __shfl_sync(0xFFFFFFFFu, sq, 0);
        mx = __shfl_sync(0xFFFFFFFFu, mx, 0);
        mi = __shfl_sync(0xFFFFFFFFu, mi, 0);

        const float* __restrict__ lab = labels + ((size_t)b * K + k) * 11;

        float part = 0.0f;
        if (lane < C) {
            const float v = __ldg(&lb_preds[((size_t)bs * C + lane) * HW + mi]);
            const float d = v - __ldg(&lab[lane]);
            part = d * d;
        }
        #pragma unroll
        for (int off = 8; off > 0; off >>= 1)
            part += __shfl_down_sync(0xFFFFFFFFu, part, off);

        if (lane == 0) {
            const float gx = __ldg(&lab[9]);
            const float gy = __ldg(&lab[10]);
            const bool valid = (gx >= 0.0f) && (gy >= 0.0f) &&
                               (gx < (float)H) && (gy < (float)W);
            const int x = mi / W;   // H == W == 128: pos == idx
            const int y = mi % W;
            const float dx = gx - (float)x;
            const float dy = gy - (float)y;
            const float cf = 1.0f - mx;
            const float lb = valid ? (part + dx * dx + dy * dy + cf * cf) : 0.0f;

            atomicAdd(&out[bs],      sq);  // hm_loss [B,S]
            atomicAdd(&out[BS + bs], lb);  // lb_loss [B,S]
        }
    }
}

extern "C" void kernel_launch(void* const* d_in, const int* in_sizes, int n_in,
                              void* d_out, int out_size) {
    const float* hm_preds = (const float*)d_in[0];  // [B,S,K,H,W]
    const float* lb_preds = (const float*)d_in[1];  // [B,S,C,H,W]
    const float* heatmaps = (const float*)d_in[2];  // [B,K,H,W]
    const float* labels   = (const float*)d_in[3];  // [B,K,11]
    float* out = (float*)d_out;

    kp_zero_kernel<<<1, 2 * BS>>>(out);
    kp_fused_kernel<<<BSK, 256>>>(hm_preds, lb_preds, heatmaps, labels, out);
}

// round 8
// speedup vs baseline: 1.0920x; 1.0920x over previous
#include <cuda_runtime.h>
#include <math_constants.h>

// Problem constants
constexpr int B = 32, S = 4, K = 11, C = 9, H = 128, W = 128;
constexpr int HW = H * W;          // 16384
constexpr int BSK = B * S * K;     // 1408
constexpr int BS = B * S;          // 128

// Cross-block scratch (device globals; counters are never reset -> use mod-K
// arrival detection so graph replays are safe).
__device__ float g_hm[BSK];          // per-(b,s,k) heatmap-loss partial
__device__ float g_lb[BSK];          // per-(b,s,k) label-loss partial
__device__ unsigned int g_count[BS]; // per-(b,s) arrival counter (monotonic)

// Single fused kernel: one block per (b,s,k).
//  - streams pred vs gt: sumsq + argmax (first-index tiebreak)
//  - warp0 computes this block's label-loss term (9 gathers at argmax)
//  - publishes partials; the 11th arriving block per (b,s) sums K partials
//    in fixed order and writes both outputs (no atomics on out, no zero pass)
__global__ __launch_bounds__(256) void kp_fused_kernel(
    const float* __restrict__ hm_preds,   // [B,S,K,H,W]
    const float* __restrict__ lb_preds,   // [B,S,C,H,W]
    const float* __restrict__ heatmaps,   // [B,K,H,W]
    const float* __restrict__ labels,     // [B,K,11]
    float* __restrict__ out)              // [2*B*S]: [hm | lb]
{
    const int blk = blockIdx.x;           // b*S*K + s*K + k
    const int k = blk % K;
    const int bs = blk / K;               // b*S + s
    const int b = bs / S;

    const float4* __restrict__ p =
        reinterpret_cast<const float4*>(hm_preds + (size_t)blk * HW);
    const float4* __restrict__ g =
        reinterpret_cast<const float4*>(heatmaps + ((size_t)b * K + k) * HW);

    const int tid = threadIdx.x;

    float sq = 0.0f;
    float mx = -CUDART_INF_F;
    int   mi = 0;

    // HW/4 = 4096 float4s, 256 threads -> 16 iterations/thread
    #pragma unroll 4
    for (int i = tid; i < HW / 4; i += 256) {
        const float4 pv = __ldcs(&p[i]);   // streaming: read once, evict first
        const float4 gv = __ldg(&g[i]);    // re-read x4 across s: keep in L2
        float d0 = pv.x - gv.x, d1 = pv.y - gv.y;
        float d2 = pv.z - gv.z, d3 = pv.w - gv.w;
        sq += d0 * d0 + d1 * d1 + d2 * d2 + d3 * d3;
        const int base = i * 4;
        // strict > keeps the lowest index within this thread (indices ascend)
        if (pv.x > mx) { mx = pv.x; mi = base;     }
        if (pv.y > mx) { mx = pv.y; mi = base + 1; }
        if (pv.z > mx) { mx = pv.z; mi = base + 2; }
        if (pv.w > mx) { mx = pv.w; mi = base + 3; }
    }

    // Warp reduction (sum + argmax with first-index tiebreak)
    #pragma unroll
    for (int off = 16; off > 0; off >>= 1) {
        sq += __shfl_down_sync(0xFFFFFFFFu, sq, off);
        float omx = __shfl_down_sync(0xFFFFFFFFu, mx, off);
        int   omi = __shfl_down_sync(0xFFFFFFFFu, mi, off);
        if (omx > mx || (omx == mx && omi < mi)) { mx = omx; mi = omi; }
    }

    __shared__ float s_sq[8];
    __shared__ float s_mx[8];
    __shared__ int   s_mi[8];
    __shared__ int   s_last;
    const int wid = tid >> 5, lane = tid & 31;
    if (lane == 0) { s_sq[wid] = sq; s_mx[wid] = mx; s_mi[wid] = mi; }
    __syncthreads();

    if (wid == 0) {
        sq = (lane < 8) ? s_sq[lane] : 0.0f;
        mx = (lane < 8) ? s_mx[lane] : -CUDART_INF_F;
        mi = (lane < 8) ? s_mi[lane] : 0x7FFFFFFF;
        #pragma unroll
        for (int off = 4; off > 0; off >>= 1) {
            sq += __shfl_down_sync(0xFFFFFFFFu, sq, off);
            float omx = __shfl_down_sync(0xFFFFFFFFu, mx, off);
            int   omi = __shfl_down_sync(0xFFFFFFFFu, mi, off);
            if (omx > mx || (omx == mx && omi < mi)) { mx = omx; mi = omi; }
        }

        // ---- This block's label-loss term: broadcast within warp 0 ----
        sq = __shfl_sync(0xFFFFFFFFu, sq, 0);
        mx = __shfl_sync(0xFFFFFFFFu, mx, 0);
        mi = __shfl_sync(0xFFFFFFFFu, mi, 0);

        const float* __restrict__ lab = labels + ((size_t)b * K + k) * 11;

        // lanes 0..8: one class-channel gather each at the argmax position
        float part = 0.0f;
        if (lane < C) {
            const float v = __ldg(&lb_preds[((size_t)bs * C + lane) * HW + mi]);
            const float d = v - __ldg(&lab[lane]);
            part = d * d;
        }
        #pragma unroll
        for (int off = 8; off > 0; off >>= 1)
            part += __shfl_down_sync(0xFFFFFFFFu, part, off);

        if (lane == 0) {
            const float gx = __ldg(&lab[9]);
            const float gy = __ldg(&lab[10]);
            const bool valid = (gx >= 0.0f) && (gy >= 0.0f) &&
                               (gx < (float)H) && (gy < (float)W);
            const int x = mi / W;   // H == W == 128: pos == idx
            const int y = mi % W;
            const float dx = gx - (float)x;
            const float dy = gy - (float)y;
            const float cf = 1.0f - mx;
            const float lb = valid ? (part + dx * dx + dy * dy + cf * cf) : 0.0f;

            // Publish partials, then bump the per-(b,s) arrival counter.
            g_hm[blk] = sq;
            g_lb[blk] = lb;
            __threadfence();
            const unsigned int old = atomicAdd(&g_count[bs], 1u);
            s_last = (old % K == K - 1);   // 11th arrival this launch
        }
    }
    __syncthreads();

    // Last-arriving block for this (b,s): fixed-order sum over k -> out.
    if (s_last && tid == 0) {
        const int base = bs * K;
        float hsum = 0.0f, lsum = 0.0f;
        #pragma unroll
        for (int kk = 0; kk < K; kk++) {
            hsum += __ldcg(&g_hm[base + kk]);  // L1-bypassing loads: partials
            lsum += __ldcg(&g_lb[base + kk]);  // were written by other SMs
        }
        out[bs]      = hsum;   // hm_loss [B,S]
        out[BS + bs] = lsum;   // lb_loss [B,S]
    }
}

extern "C" void kernel_launch(void* const* d_in, const int* in_sizes, int n_in,
                              void* d_out, int out_size) {
    const float* hm_preds = (const float*)d_in[0];  // [B,S,K,H,W]
    const float* lb_preds = (const float*)d_in[1];  // [B,S,C,H,W]
    const float* heatmaps = (const float*)d_in[2];  // [B,K,H,W]
    const float* labels   = (const float*)d_in[3];  // [B,K,11]
    float* out = (float*)d_out;

    kp_fused_kernel<<<BSK, 256>>>(hm_preds, lb_preds, heatmaps, labels, out);
}

// round 9
// speedup vs baseline: 1.1104x; 1.0169x over previous
#include <cuda_runtime.h>
#include <math_constants.h>

// Problem constants
constexpr int B = 32, S = 4, K = 11, C = 9, H = 128, W = 128;
constexpr int HW = H * W;          // 16384
constexpr int BSK = B * S * K;     // 1408
constexpr int BS = B * S;          // 128

// Cross-launch scratch (device globals zero-init at load; g_acc is drained
// back to 0.0f by atomicExch each launch; g_count is monotonic with mod-K
// arrival detection -> graph-replay safe, no zero pass needed).
__device__ float        g_acc[2 * BS];   // [hm partial sums | lb partial sums]
__device__ unsigned int g_count[BS];     // per-(b,s) arrival counter

// Single fused kernel: one block per (b,s,k).
__global__ __launch_bounds__(256) void kp_fused_kernel(
    const float* __restrict__ hm_preds,   // [B,S,K,H,W]
    const float* __restrict__ lb_preds,   // [B,S,C,H,W]
    const float* __restrict__ heatmaps,   // [B,K,H,W]
    const float* __restrict__ labels,     // [B,K,11]
    float* __restrict__ out)              // [2*B*S]: [hm | lb]
{
    const int blk = blockIdx.x;           // b*S*K + s*K + k
    const int k = blk % K;
    const int bs = blk / K;               // b*S + s
    const int b = bs / S;

    const float4* __restrict__ p =
        reinterpret_cast<const float4*>(hm_preds + (size_t)blk * HW);
    const float4* __restrict__ g =
        reinterpret_cast<const float4*>(heatmaps + ((size_t)b * K + k) * HW);

    const int tid = threadIdx.x;

    float sq = 0.0f;
    float mx = -CUDART_INF_F;
    int   mi = 0;

    // HW/4 = 4096 float4s, 256 threads -> 16 iterations/thread
    #pragma unroll 4
    for (int i = tid; i < HW / 4; i += 256) {
        const float4 pv = __ldcs(&p[i]);   // streaming: read once, evict first
        const float4 gv = __ldg(&g[i]);    // re-read x4 across s: keep in L2
        float d0 = pv.x - gv.x, d1 = pv.y - gv.y;
        float d2 = pv.z - gv.z, d3 = pv.w - gv.w;
        sq += d0 * d0 + d1 * d1 + d2 * d2 + d3 * d3;
        const int base = i * 4;
        // strict > keeps the lowest index within this thread (indices ascend)
        if (pv.x > mx) { mx = pv.x; mi = base;     }
        if (pv.y > mx) { mx = pv.y; mi = base + 1; }
        if (pv.z > mx) { mx = pv.z; mi = base + 2; }
        if (pv.w > mx) { mx = pv.w; mi = base + 3; }
    }

    // Warp reduction (sum + argmax with first-index tiebreak)
    #pragma unroll
    for (int off = 16; off > 0; off >>= 1) {
        sq += __shfl_down_sync(0xFFFFFFFFu, sq, off);
        float omx = __shfl_down_sync(0xFFFFFFFFu, mx, off);
        int   omi = __shfl_down_sync(0xFFFFFFFFu, mi, off);
        if (omx > mx || (omx == mx && omi < mi)) { mx = omx; mi = omi; }
    }

    __shared__ float s_sq[8];
    __shared__ float s_mx[8];
    __shared__ int   s_mi[8];
    const int wid = tid >> 5, lane = tid & 31;
    if (lane == 0) { s_sq[wid] = sq; s_mx[wid] = mx; s_mi[wid] = mi; }
    __syncthreads();

    if (wid == 0) {
        sq = (lane < 8) ? s_sq[lane] : 0.0f;
        mx = (lane < 8) ? s_mx[lane] : -CUDART_INF_F;
        mi = (lane < 8) ? s_mi[lane] : 0x7FFFFFFF;
        #pragma unroll
        for (int off = 4; off > 0; off >>= 1) {
            sq += __shfl_down_sync(0xFFFFFFFFu, sq, off);
            float omx = __shfl_down_sync(0xFFFFFFFFu, mx, off);
            int   omi = __shfl_down_sync(0xFFFFFFFFu, mi, off);
            if (omx > mx || (omx == mx && omi < mi)) { mx = omx; mi = omi; }
        }

        // ---- Label-loss term for this block: broadcast within warp 0 ----
        sq = __shfl_sync(0xFFFFFFFFu, sq, 0);
        mx = __shfl_sync(0xFFFFFFFFu, mx, 0);
        mi = __shfl_sync(0xFFFFFFFFu, mi, 0);

        const float* __restrict__ lab = labels + ((size_t)b * K + k) * 11;

        // lanes 0..8: one class-channel gather each at the argmax position
        float part = 0.0f;
        if (lane < C) {
            const float v = __ldg(&lb_preds[((size_t)bs * C + lane) * HW + mi]);
            const float d = v - __ldg(&lab[lane]);
            part = d * d;
        }
        #pragma unroll
        for (int off = 8; off > 0; off >>= 1)
            part += __shfl_down_sync(0xFFFFFFFFu, part, off);

        if (lane == 0) {
            const float gx = __ldg(&lab[9]);
            const float gy = __ldg(&lab[10]);
            const bool valid = (gx >= 0.0f) && (gy >= 0.0f) &&
                               (gx < (float)H) && (gy < (float)W);
            const int x = mi / W;   // H == W == 128: pos == idx
            const int y = mi % W;
            const float dx = gx - (float)x;
            const float dy = gy - (float)y;
            const float cf = 1.0f - mx;
            const float lb = valid ? (part + dx * dx + dy * dy + cf * cf) : 0.0f;

            // Accumulate into self-resetting scratch; 11th arrival drains
            // the sums (atomicExch reads + re-zeros for the next replay)
            // and writes the outputs.
            atomicAdd(&g_acc[bs],      sq);
            atomicAdd(&g_acc[BS + bs], lb);
            __threadfence();
            const unsigned int old = atomicAdd(&g_count[bs], 1u);
            if (old % K == K - 1) {          // last of the 11 this launch
                const float hs = atomicExch(&g_acc[bs],      0.0f);
                const float ls = atomicExch(&g_acc[BS + bs], 0.0f);
                out[bs]      = hs;   // hm_loss [B,S]
                out[BS + bs] = ls;   // lb_loss [B,S]
            }
        }
    }
}

extern "C" void kernel_launch(void* const* d_in, const int* in_sizes, int n_in,
                              void* d_out, int out_size) {
    const float* hm_preds = (const float*)d_in[0];  // [B,S,K,H,W]
    const float* lb_preds = (const float*)d_in[1];  // [B,S,C,H,W]
    const float* heatmaps = (const float*)d_in[2];  // [B,K,H,W]
    const float* labels   = (const float*)d_in[3];  // [B,K,11]
    float* out = (float*)d_out;

    kp_fused_kernel<<<BSK, 256>>>(hm_preds, lb_preds, heatmaps, labels, out);
}

// round 11
// speedup vs baseline: 1.1892x; 1.0709x over previous
#include <cuda_runtime.h>
#include <math_constants.h>
#include <cstdint>

// Problem constants
constexpr int B = 32, S = 4, K = 11, C = 9, H = 128, W = 128;
constexpr int HW = H * W;          // 16384
constexpr int BSK = B * S * K;     // 1408
constexpr int BS = B * S;          // 128

// Zero-init the output (poisoned by harness; we accumulate with atomics).
__global__ __launch_bounds__(256) void kp_zero_kernel(float* __restrict__ out) {
    out[threadIdx.x] = 0.0f;       // exactly 2*BS = 256 elements
}

// 32-byte evict_last load (sm_103a requires .v4.b64 width for this hint):
// pins heatmap lines at max L2 retention priority so they survive across
// graph replays while preds stream through with evict-first.
__device__ __forceinline__ void ldg_evict_last8(const float* p,
                                                float4& a, float4& b) {
    uint64_t r0, r1, r2, r3;
    asm volatile("ld.global.nc.L2::evict_last.v4.b64 {%0,%1,%2,%3}, [%4];"
                 : "=l"(r0), "=l"(r1), "=l"(r2), "=l"(r3) : "l"(p));
    a.x = __uint_as_float((uint32_t)r0); a.y = __uint_as_float((uint32_t)(r0 >> 32));
    a.z = __uint_as_float((uint32_t)r1); a.w = __uint_as_float((uint32_t)(r1 >> 32));
    b.x = __uint_as_float((uint32_t)r2); b.y = __uint_as_float((uint32_t)(r2 >> 32));
    b.z = __uint_as_float((uint32_t)r3); b.w = __uint_as_float((uint32_t)(r3 >> 32));
}

// One block per (b,s,k): fused squared-diff reduction + argmax + label-loss
// epilogue (scattered gathers + atomic accumulation into out).
__global__ __launch_bounds__(256) void kp_fused_kernel(
    const float* __restrict__ hm_preds,   // [B,S,K,H,W]
    const float* __restrict__ lb_preds,   // [B,S,C,H,W]
    const float* __restrict__ heatmaps,   // [B,K,H,W]
    const float* __restrict__ labels,     // [B,K,11]
    float* __restrict__ out)              // [2*B*S]: [hm | lb]
{
    const int blk = blockIdx.x;           // b*S*K + s*K + k
    const int k = blk % K;
    const int bs = blk / K;               // b*S + s
    const int b = bs / S;

    const float4* __restrict__ p =
        reinterpret_cast<const float4*>(hm_preds + (size_t)blk * HW);
    const float* __restrict__ g = heatmaps + ((size_t)b * K + k) * HW;

    const int tid = threadIdx.x;

    float sq = 0.0f;
    float mx = -CUDART_INF_F;
    int   mi = 0;

    // HW/8 = 2048 8-float chunks, 256 threads -> 8 iterations/thread.
    // Per iter: 1x 32B evict-last gt load + 2x 16B evict-first pred loads.
    #pragma unroll 4
    for (int i = tid; i < HW / 8; i += 256) {
        float4 g0, g1;
        ldg_evict_last8(g + (size_t)i * 8, g0, g1);
        const float4 p0 = __ldcs(&p[i * 2]);
        const float4 p1 = __ldcs(&p[i * 2 + 1]);

        float d0 = p0.x - g0.x, d1 = p0.y - g0.y;
        float d2 = p0.z - g0.z, d3 = p0.w - g0.w;
        float e0 = p1.x - g1.x, e1 = p1.y - g1.y;
        float e2 = p1.z - g1.z, e3 = p1.w - g1.w;
        sq += d0 * d0 + d1 * d1 + d2 * d2 + d3 * d3;
        sq += e0 * e0 + e1 * e1 + e2 * e2 + e3 * e3;

        const int base = i * 8;
        // strict > keeps the lowest index within this thread (indices ascend)
        if (p0.x > mx) { mx = p0.x; mi = base;     }
        if (p0.y > mx) { mx = p0.y; mi = base + 1; }
        if (p0.z > mx) { mx = p0.z; mi = base + 2; }
        if (p0.w > mx) { mx = p0.w; mi = base + 3; }
        if (p1.x > mx) { mx = p1.x; mi = base + 4; }
        if (p1.y > mx) { mx = p1.y; mi = base + 5; }
        if (p1.z > mx) { mx = p1.z; mi = base + 6; }
        if (p1.w > mx) { mx = p1.w; mi = base + 7; }
    }

    // Warp reduction (sum + argmax with first-index tiebreak)
    #pragma unroll
    for (int off = 16; off > 0; off >>= 1) {
        sq += __shfl_down_sync(0xFFFFFFFFu, sq, off);
        float omx = __shfl_down_sync(0xFFFFFFFFu, mx, off);
        int   omi = __shfl_down_sync(0xFFFFFFFFu, mi, off);
        if (omx > mx || (omx == mx && omi < mi)) { mx = omx; mi = omi; }
    }

    __shared__ float s_sq[8];
    __shared__ float s_mx[8];
    __shared__ int   s_mi[8];
    const int wid = tid >> 5, lane = tid & 31;
    if (lane == 0) { s_sq[wid] = sq; s_mx[wid] = mx; s_mi[wid] = mi; }
    __syncthreads();

    if (wid == 0) {
        sq = (lane < 8) ? s_sq[lane] : 0.0f;
        mx = (lane < 8) ? s_mx[lane] : -CUDART_INF_F;
        mi = (lane < 8) ? s_mi[lane] : 0x7FFFFFFF;
        #pragma unroll
        for (int off = 4; off > 0; off >>= 1) {
            sq += __shfl_down_sync(0xFFFFFFFFu, sq, off);
            float omx = __shfl_down_sync(0xFFFFFFFFu, mx, off);
            int   omi = __shfl_down_sync(0xFFFFFFFFu, mi, off);
            if (omx > mx || (omx == mx && omi < mi)) { mx = omx; mi = omi; }
        }

        // ---- Label-loss epilogue, fused: broadcast result to warp 0 ----
        sq = __shfl_sync(0xFFFFFFFFu, sq, 0);
        mx = __shfl_sync(0xFFFFFFFFu, mx, 0);
        mi = __shfl_sync(0xFFFFFFFFu, mi, 0);

        const float* __restrict__ lab = labels + ((size_t)b * K + k) * 11;

        // lanes 0..8: one class-channel gather each at the argmax position
        float part = 0.0f;
        if (lane < C) {
            const float v = __ldg(&lb_preds[((size_t)bs * C + lane) * HW + mi]);
            const float d = v - __ldg(&lab[lane]);
            part = d * d;
        }
        #pragma unroll
        for (int off = 8; off > 0; off >>= 1)
            part += __shfl_down_sync(0xFFFFFFFFu, part, off);

        if (lane == 0) {
            const float gx = __ldg(&lab[9]);
            const float gy = __ldg(&lab[10]);
            const bool valid = (gx >= 0.0f) && (gy >= 0.0f) &&
                               (gx < (float)H) && (gy < (float)W);
            const int x = mi / W;  // m == H == W == 128: pos == idx
            const int y = mi % W;
            const float dx = gx - (float)x;
            const float dy = gy - (float)y;
            const float cf = 1.0f - mx;
            const float lb = valid ? (part + dx * dx + dy * dy + cf * cf) : 0.0f;

            atomicAdd(&out[bs],      sq);  // hm_loss [B,S]
            atomicAdd(&out[BS + bs], lb);  // lb_loss [B,S]
        }
    }
}

extern "C" void kernel_launch(void* const* d_in, const int* in_sizes, int n_in,
                              void* d_out, int out_size) {
    const float* hm_preds = (const float*)d_in[0];  // [B,S,K,H,W]
    const float* lb_preds = (const float*)d_in[1];  // [B,S,C,H,W]
    const float* heatmaps = (const float*)d_in[2];  // [B,K,H,W]
    const float* labels   = (const float*)d_in[3];  // [B,K,11]
    float* out = (float*)d_out;

    kp_zero_kernel<<<1, 2 * BS>>>(out);
    kp_fused_kernel<<<BSK, 256>>>(hm_preds, lb_preds, heatmaps, labels, out);
}

// round 12
// speedup vs baseline: 1.1908x; 1.0014x over previous
#include <cuda_runtime.h>
#include <math_constants.h>
#include <cstdint>

// Problem constants
constexpr int B = 32, S = 4, K = 11, C = 9, H = 128, W = 128;
constexpr int HW = H * W;          // 16384
constexpr int BSK = B * S * K;     // 1408
constexpr int BS = B * S;          // 128

// Zero-init the output (poisoned by harness; we accumulate with atomics).
__global__ __launch_bounds__(256) void kp_zero_kernel(float* __restrict__ out) {
    out[threadIdx.x] = 0.0f;       // exactly 2*BS = 256 elements
}

// 32-byte loads (sm_103a .v4.b64 class — required width for L2 hint forms).
// gt: evict_last (pin resident across graph replays).
// pred: evict_first (pure stream, don't pollute L2).
__device__ __forceinline__ void ldg_evict_last8(const float* p,
                                                float4& a, float4& b) {
    uint64_t r0, r1, r2, r3;
    asm volatile("ld.global.nc.L2::evict_last.v4.b64 {%0,%1,%2,%3}, [%4];"
                 : "=l"(r0), "=l"(r1), "=l"(r2), "=l"(r3) : "l"(p));
    a.x = __uint_as_float((uint32_t)r0); a.y = __uint_as_float((uint32_t)(r0 >> 32));
    a.z = __uint_as_float((uint32_t)r1); a.w = __uint_as_float((uint32_t)(r1 >> 32));
    b.x = __uint_as_float((uint32_t)r2); b.y = __uint_as_float((uint32_t)(r2 >> 32));
    b.z = __uint_as_float((uint32_t)r3); b.w = __uint_as_float((uint32_t)(r3 >> 32));
}
__device__ __forceinline__ void ldg_evict_first8(const float* p,
                                                 float4& a, float4& b) {
    uint64_t r0, r1, r2, r3;
    asm volatile("ld.global.nc.L2::evict_first.v4.b64 {%0,%1,%2,%3}, [%4];"
                 : "=l"(r0), "=l"(r1), "=l"(r2), "=l"(r3) : "l"(p));
    a.x = __uint_as_float((uint32_t)r0); a.y = __uint_as_float((uint32_t)(r0 >> 32));
    a.z = __uint_as_float((uint32_t)r1); a.w = __uint_as_float((uint32_t)(r1 >> 32));
    b.x = __uint_as_float((uint32_t)r2); b.y = __uint_as_float((uint32_t)(r2 >> 32));
    b.z = __uint_as_float((uint32_t)r3); b.w = __uint_as_float((uint32_t)(r3 >> 32));
}

// One block per (b,s,k): fused squared-diff reduction + argmax + label-loss
// epilogue (scattered gathers + atomic accumulation into out).
__global__ __launch_bounds__(256) void kp_fused_kernel(
    const float* __restrict__ hm_preds,   // [B,S,K,H,W]
    const float* __restrict__ lb_preds,   // [B,S,C,H,W]
    const float* __restrict__ heatmaps,   // [B,K,H,W]
    const float* __restrict__ labels,     // [B,K,11]
    float* __restrict__ out)              // [2*B*S]: [hm | lb]
{
    const int blk = blockIdx.x;           // b*S*K + s*K + k
    const int k = blk % K;
    const int bs = blk / K;               // b*S + s
    const int b = bs / S;

    const float* __restrict__ p = hm_preds + (size_t)blk * HW;
    const float* __restrict__ g = heatmaps + ((size_t)b * K + k) * HW;

    const int tid = threadIdx.x;

    float sq = 0.0f;
    float mx = -CUDART_INF_F;
    int   mi = 0;

    // HW/8 = 2048 8-float chunks, 256 threads -> 8 iterations/thread.
    // Per iter: one 32B evict-last gt load + one 32B evict-first pred load.
    #pragma unroll 4
    for (int i = tid; i < HW / 8; i += 256) {
        float4 g0, g1, p0, p1;
        ldg_evict_last8(g + (size_t)i * 8, g0, g1);
        ldg_evict_first8(p + (size_t)i * 8, p0, p1);

        float d0 = p0.x - g0.x, d1 = p0.y - g0.y;
        float d2 = p0.z - g0.z, d3 = p0.w - g0.w;
        float e0 = p1.x - g1.x, e1 = p1.y - g1.y;
        float e2 = p1.z - g1.z, e3 = p1.w - g1.w;
        sq += d0 * d0 + d1 * d1 + d2 * d2 + d3 * d3;
        sq += e0 * e0 + e1 * e1 + e2 * e2 + e3 * e3;

        const int base = i * 8;
        // strict > keeps the lowest index within this thread (indices ascend)
        if (p0.x > mx) { mx = p0.x; mi = base;     }
        if (p0.y > mx) { mx = p0.y; mi = base + 1; }
        if (p0.z > mx) { mx = p0.z; mi = base + 2; }
        if (p0.w > mx) { mx = p0.w; mi = base + 3; }
        if (p1.x > mx) { mx = p1.x; mi = base + 4; }
        if (p1.y > mx) { mx = p1.y; mi = base + 5; }
        if (p1.z > mx) { mx = p1.z; mi = base + 6; }
        if (p1.w > mx) { mx = p1.w; mi = base + 7; }
    }

    // Warp reduction (sum + argmax with first-index tiebreak)
    #pragma unroll
    for (int off = 16; off > 0; off >>= 1) {
        sq += __shfl_down_sync(0xFFFFFFFFu, sq, off);
        float omx = __shfl_down_sync(0xFFFFFFFFu, mx, off);
        int   omi = __shfl_down_sync(0xFFFFFFFFu, mi, off);
        if (omx > mx || (omx == mx && omi < mi)) { mx = omx; mi = omi; }
    }

    __shared__ float s_sq[8];
    __shared__ float s_mx[8];
    __shared__ int   s_mi[8];
    const int wid = tid >> 5, lane = tid & 31;
    if (lane == 0) { s_sq[wid] = sq; s_mx[wid] = mx; s_mi[wid] = mi; }
    __syncthreads();

    if (wid == 0) {
        sq = (lane < 8) ? s_sq[lane] : 0.0f;
        mx = (lane < 8) ? s_mx[lane] : -CUDART_INF_F;
        mi = (lane < 8) ? s_mi[lane] : 0x7FFFFFFF;
        #pragma unroll
        for (int off = 4; off > 0; off >>= 1) {
            sq += __shfl_down_sync(0xFFFFFFFFu, sq, off);
            float omx = __shfl_down_sync(0xFFFFFFFFu, mx, off);
            int   omi = __shfl_down_sync(0xFFFFFFFFu, mi, off);
            if (omx > mx || (omx == mx && omi < mi)) { mx = omx; mi = omi; }
        }

        // ---- Label-loss epilogue, fused: broadcast result to warp 0 ----
        sq = __shfl_sync(0xFFFFFFFFu, sq, 0);
        mx = __shfl_sync(0xFFFFFFFFu, mx, 0);
        mi = __shfl_sync(0xFFFFFFFFu, mi, 0);

        const float* __restrict__ lab = labels + ((size_t)b * K + k) * 11;

        // lanes 0..8: one class-channel gather each at the argmax position
        float part = 0.0f;
        if (lane < C) {
            const float v = __ldg(&lb_preds[((size_t)bs * C + lane) * HW + mi]);
            const float d = v - __ldg(&lab[lane]);
            part = d * d;
        }
        #pragma unroll
        for (int off = 8; off > 0; off >>= 1)
            part += __shfl_down_sync(0xFFFFFFFFu, part, off);

        if (lane == 0) {
            const float gx = __ldg(&lab[9]);
            const float gy = __ldg(&lab[10]);
            const bool valid = (gx >= 0.0f) && (gy >= 0.0f) &&
                               (gx < (float)H) && (gy < (float)W);
            const int x = mi / W;  // m == H == W == 128: pos == idx
            const int y = mi % W;
            const float dx = gx - (float)x;
            const float dy = gy - (float)y;
            const float cf = 1.0f - mx;
            const float lb = valid ? (part + dx * dx + dy * dy + cf * cf) : 0.0f;

            atomicAdd(&out[bs],      sq);  // hm_loss [B,S]
            atomicAdd(&out[BS + bs], lb);  // lb_loss [B,S]
        }
    }
}

extern "C" void kernel_launch(void* const* d_in, const int* in_sizes, int n_in,
                              void* d_out, int out_size) {
    const float* hm_preds = (const float*)d_in[0];  // [B,S,K,H,W]
    const float* lb_preds = (const float*)d_in[1];  // [B,S,C,H,W]
    const float* heatmaps = (const float*)d_in[2];  // [B,K,H,W]
    const float* labels   = (const float*)d_in[3];  // [B,K,11]
    float* out = (float*)d_out;

    kp_zero_kernel<<<1, 2 * BS>>>(out);
    kp_fused_kernel<<<BSK, 256>>>(hm_preds, lb_preds, heatmaps, labels, out);
}